// round 4
// baseline (speedup 1.0000x reference)
#include <cuda_runtime.h>
#include <math.h>
#include <stdint.h>

constexpr int NSEQ = 384;
constexpr int CIN  = 128;
constexpr int NH   = 4;
constexpr int CHD  = 32;
constexpr int NTOK = NSEQ * NSEQ;
constexpr float QSCALE = 0.17677669529663687f;

// ---- scratch ----
__device__ float g_zn[NTOK * CIN];
__device__ float g_q [NTOK * CIN];
__device__ float g_k [NTOK * CIN];
__device__ float g_v [NTOK * CIN];
__device__ float g_g [NTOK * CIN];
__device__ float g_og[NTOK * CIN];
__device__ float g_tri[NH * NTOK];   // [h][q*NSEQ+k]

__device__ __forceinline__ float to_tf32(float x) {
    float r; asm("cvt.rna.tf32.f32 %0, %1;" : "=f"(r) : "f"(x)); return r;
}
__device__ __forceinline__ void mma8(float* d, const uint32_t* a, const uint32_t* b) {
    asm volatile(
        "mma.sync.aligned.m16n8k8.row.col.f32.tf32.tf32.f32 "
        "{%0,%1,%2,%3},{%4,%5,%6,%7},{%8,%9},{%0,%1,%2,%3};"
        : "+f"(d[0]), "+f"(d[1]), "+f"(d[2]), "+f"(d[3])
        : "r"(a[0]), "r"(a[1]), "r"(a[2]), "r"(a[3]), "r"(b[0]), "r"(b[1]));
}

// ============================================================
// Kernel 1: LayerNorm + tri. 256 thr = 8 warps, warp per token.
// ============================================================
__global__ __launch_bounds__(256)
void ln_tri_kernel(const float* __restrict__ z,
                   const float* __restrict__ ln_w,
                   const float* __restrict__ ln_b,
                   const float* __restrict__ w_tri) {
    int warp = threadIdx.x >> 5, lane = threadIdx.x & 31;
    int t = blockIdx.x * 8 + warp;

    float4 x = *(const float4*)&z[(size_t)t * CIN + lane * 4];
    float v1 = x.x + x.y + x.z + x.w;
    float v2 = x.x * x.x + x.y * x.y + x.z * x.z + x.w * x.w;
    #pragma unroll
    for (int off = 16; off; off >>= 1) {
        v1 += __shfl_xor_sync(~0u, v1, off);
        v2 += __shfl_xor_sync(~0u, v2, off);
    }
    float mean = v1 * (1.0f / CIN);
    float var  = v2 * (1.0f / CIN) - mean * mean;
    float rs   = rsqrtf(var + 1e-5f);

    float4 w = *(const float4*)&ln_w[lane * 4];
    float4 b = *(const float4*)&ln_b[lane * 4];
    float4 zn;
    zn.x = (x.x - mean) * rs * w.x + b.x;
    zn.y = (x.y - mean) * rs * w.y + b.y;
    zn.z = (x.z - mean) * rs * w.z + b.z;
    zn.w = (x.w - mean) * rs * w.w + b.w;
    *(float4*)&g_zn[(size_t)t * CIN + lane * 4] = zn;

    float p[4] = {};
    float zc[4] = { zn.x, zn.y, zn.z, zn.w };
    #pragma unroll
    for (int cc = 0; cc < 4; cc++) {
        float4 wt = *(const float4*)&w_tri[(lane * 4 + cc) * NH];
        p[0] += zc[cc] * wt.x; p[1] += zc[cc] * wt.y;
        p[2] += zc[cc] * wt.z; p[3] += zc[cc] * wt.w;
    }
    #pragma unroll
    for (int off = 16; off; off >>= 1)
        #pragma unroll
        for (int h = 0; h < 4; h++) p[h] += __shfl_xor_sync(~0u, p[h], off);
    if (lane == 0)
        #pragma unroll
        for (int h = 0; h < 4; h++) g_tri[(size_t)h * NTOK + t] = p[h];
}

// ============================================================
// Kernel 2: projections. BM=64, BN=128, BK=128, 2 CTAs/SM.
// ============================================================
constexpr int AS = 132, BS = 136;

__global__ __launch_bounds__(256, 2)
void proj_tc(const float* __restrict__ wq, const float* __restrict__ wk,
             const float* __restrict__ wv, const float* __restrict__ wg) {
    extern __shared__ float sm[];
    float* As = sm;              // 64 x AS
    float* Bs = sm + 64 * AS;    // 128 x BS
    int tid = threadIdx.x, lane = tid & 31, warp = tid >> 5;
    int g = lane >> 2, t = lane & 3;
    int sel = blockIdx.x;
    const float* W = (sel == 0) ? wq : (sel == 1) ? wk : (sel == 2) ? wv : wg;
    int m0 = blockIdx.y * 64;

    const float4* Ag = (const float4*)(g_zn + (size_t)m0 * CIN);
    const float4* Bg = (const float4*)W;
    #pragma unroll
    for (int e = 0; e < 8; e++) {
        int f = tid + e * 256;
        int row = f >> 5, c4 = (f & 31) * 4;
        float4 va = Ag[f];
        As[row * AS + c4 + 0] = to_tf32(va.x); As[row * AS + c4 + 1] = to_tf32(va.y);
        As[row * AS + c4 + 2] = to_tf32(va.z); As[row * AS + c4 + 3] = to_tf32(va.w);
    }
    #pragma unroll
    for (int e = 0; e < 16; e++) {
        int f = tid + e * 256;
        int row = f >> 5, c4 = (f & 31) * 4;
        float4 vb = Bg[f];
        Bs[row * BS + c4 + 0] = to_tf32(vb.x); Bs[row * BS + c4 + 1] = to_tf32(vb.y);
        Bs[row * BS + c4 + 2] = to_tf32(vb.z); Bs[row * BS + c4 + 3] = to_tf32(vb.w);
    }
    __syncthreads();

    int wm = warp >> 2, wn = warp & 3;   // 2 x 4; warp tile 32 x 32
    float acc[2][4][4] = {};
    #pragma unroll
    for (int kc = 0; kc < 16; kc++) {
        uint32_t a[2][4];
        #pragma unroll
        for (int mt = 0; mt < 2; mt++) {
            const uint32_t* ap = (const uint32_t*)(As + (wm * 32 + mt * 16 + g) * AS + kc * 8 + t);
            a[mt][0] = ap[0]; a[mt][1] = ap[8 * AS]; a[mt][2] = ap[4]; a[mt][3] = ap[8 * AS + 4];
        }
        #pragma unroll
        for (int nt = 0; nt < 4; nt++) {
            const uint32_t* bp = (const uint32_t*)(Bs + (kc * 8 + t) * BS + wn * 32 + nt * 8 + g);
            uint32_t b[2] = { bp[0], bp[4 * BS] };
            mma8(acc[0][nt], a[0], b);
            mma8(acc[1][nt], a[1], b);
        }
    }
    #pragma unroll
    for (int mt = 0; mt < 2; mt++)
        #pragma unroll
        for (int nt = 0; nt < 4; nt++)
            #pragma unroll
            for (int hf = 0; hf < 2; hf++) {
                int gm  = m0 + wm * 32 + mt * 16 + g + hf * 8;
                int col = wn * 32 + nt * 8 + 2 * t;
                float c0 = acc[mt][nt][hf * 2 + 0], c1 = acc[mt][nt][hf * 2 + 1];
                size_t idx = (size_t)gm * CIN + col;
                if (sel == 0) {
                    float2 o = { c0 * QSCALE, c1 * QSCALE };
                    *(float2*)&g_q[idx] = o;
                } else if (sel == 1) {
                    float2 o = { c0, c1 };
                    *(float2*)&g_k[idx] = o;
                } else if (sel == 2) {
                    float2 o = { c0, c1 };
                    *(float2*)&g_v[idx] = o;
                } else {
                    float2 o = { 1.0f / (1.0f + __expf(-c0)), 1.0f / (1.0f + __expf(-c1)) };
                    *(float2*)&g_g[idx] = o;
                }
            }
}

// ============================================================
// Kernel 3: attention. 512 threads, 6 passes of 64 q rows.
// QK: 16 warps 4(M) x 4(N), warp tile 16 x 96.
// Softmax: warp-local max/sum (flash-style rescale at combine).
// P: C-frag -> A-frag via quad shuffles (no smem round trip).
// AV: per-warp over its 96-k slice, partials combined in smem.
// ============================================================
constexpr int KS_S = 36, VS_S = 40, QS_S = 36, OB_S = 36;

__global__ __launch_bounds__(512, 1)
void attn_tc(const float* __restrict__ mask) {
    int i = blockIdx.x, h = blockIdx.y;
    extern __shared__ float sm[];
    float* Ks   = sm;                       // 384*36
    float* Vs   = Ks + NSEQ * KS_S;         // 384*40
    float* Qs   = Vs + NSEQ * VS_S;         // 64*36
    float* bsm  = Qs + 64 * QS_S;           // 384
    float* redA = bsm + NSEQ;               // 64*4 local max
    float* redB = redA + 256;               // 64*4 local sum
    float* obuf = redB + 256;               // 4 * 64 * 36

    int tid = threadIdx.x, lane = tid & 31, warp = tid >> 5;
    int g = lane >> 2, t = lane & 3;
    int wm = warp & 3, wn = warp >> 2;

    // ---- load K, V (tf32) ----
    #pragma unroll
    for (int e = 0; e < 6; e++) {
        int f = tid + e * 512;                  // 3072 float4s
        int row = f >> 3, c4 = (f & 7) * 4;
        size_t src = (size_t)(i * NSEQ + row) * CIN + h * CHD + c4;
        float4 vk = *(const float4*)&g_k[src];
        Ks[row * KS_S + c4 + 0] = to_tf32(vk.x); Ks[row * KS_S + c4 + 1] = to_tf32(vk.y);
        Ks[row * KS_S + c4 + 2] = to_tf32(vk.z); Ks[row * KS_S + c4 + 3] = to_tf32(vk.w);
        float4 vv = *(const float4*)&g_v[src];
        Vs[row * VS_S + c4 + 0] = to_tf32(vv.x); Vs[row * VS_S + c4 + 1] = to_tf32(vv.y);
        Vs[row * VS_S + c4 + 2] = to_tf32(vv.z); Vs[row * VS_S + c4 + 3] = to_tf32(vv.w);
    }
    if (tid < NSEQ)
        bsm[tid] = 1e9f * (mask[i * NSEQ + tid] - 1.0f);

    const float* trih = g_tri + (size_t)h * NTOK;

    for (int pass = 0; pass < 6; pass++) {
        int q0 = pass * 64;

        // ---- fill Qs (64 x 32) ----
        {
            int row = tid >> 3, c4 = (tid & 7) * 4;
            size_t src = (size_t)(i * NSEQ + q0 + row) * CIN + h * CHD + c4;
            float4 v = *(const float4*)&g_q[src];
            Qs[row * QS_S + c4 + 0] = to_tf32(v.x); Qs[row * QS_S + c4 + 1] = to_tf32(v.y);
            Qs[row * QS_S + c4 + 2] = to_tf32(v.z); Qs[row * QS_S + c4 + 3] = to_tf32(v.w);
        }
        __syncthreads();   // Qs ready (and, for pass 0, K/V/bsm; later: obuf reuse)

        // ---- QK: S[16 x 96] per warp ----
        float s[12][4] = {};
        #pragma unroll
        for (int kc = 0; kc < 4; kc++) {
            const uint32_t* ap = (const uint32_t*)(Qs + (wm * 16 + g) * QS_S + kc * 8 + t);
            uint32_t a[4] = { ap[0], ap[8 * QS_S], ap[4], ap[8 * QS_S + 4] };
            #pragma unroll
            for (int nt = 0; nt < 12; nt++) {
                const uint32_t* bp = (const uint32_t*)(Ks + (wn * 96 + nt * 8 + g) * KS_S + kc * 8 + t);
                uint32_t b[2] = { bp[0], bp[4] };
                mma8(s[nt], a, b);
            }
        }

        // ---- biases + warp-local row max ----
        int qa = q0 + wm * 16 + g, qb = qa + 8;
        float rm0 = -1e30f, rm1 = -1e30f;
        #pragma unroll
        for (int nt = 0; nt < 12; nt++) {
            int k = wn * 96 + nt * 8 + 2 * t;
            float b0 = bsm[k], b1 = bsm[k + 1];
            float2 t0 = *(const float2*)&trih[(size_t)qa * NSEQ + k];
            float2 t1 = *(const float2*)&trih[(size_t)qb * NSEQ + k];
            s[nt][0] += b0 + t0.x; s[nt][1] += b1 + t0.y;
            s[nt][2] += b0 + t1.x; s[nt][3] += b1 + t1.y;
            rm0 = fmaxf(rm0, fmaxf(s[nt][0], s[nt][1]));
            rm1 = fmaxf(rm1, fmaxf(s[nt][2], s[nt][3]));
        }
        rm0 = fmaxf(rm0, __shfl_xor_sync(~0u, rm0, 1));
        rm0 = fmaxf(rm0, __shfl_xor_sync(~0u, rm0, 2));
        rm1 = fmaxf(rm1, __shfl_xor_sync(~0u, rm1, 1));
        rm1 = fmaxf(rm1, __shfl_xor_sync(~0u, rm1, 2));

        // ---- exp (local max) + warp-local sums ----
        float sum0 = 0.f, sum1 = 0.f;
        #pragma unroll
        for (int nt = 0; nt < 12; nt++) {
            s[nt][0] = __expf(s[nt][0] - rm0); sum0 += s[nt][0];
            s[nt][1] = __expf(s[nt][1] - rm0); sum0 += s[nt][1];
            s[nt][2] = __expf(s[nt][2] - rm1); sum1 += s[nt][2];
            s[nt][3] = __expf(s[nt][3] - rm1); sum1 += s[nt][3];
        }
        sum0 += __shfl_xor_sync(~0u, sum0, 1); sum0 += __shfl_xor_sync(~0u, sum0, 2);
        sum1 += __shfl_xor_sync(~0u, sum1, 1); sum1 += __shfl_xor_sync(~0u, sum1, 2);
        if (t == 0) {
            redA[(wm * 16 + g) * 4 + wn]     = rm0;
            redA[(wm * 16 + g + 8) * 4 + wn] = rm1;
            redB[(wm * 16 + g) * 4 + wn]     = sum0;
            redB[(wm * 16 + g + 8) * 4 + wn] = sum1;
        }

        // ---- AV over this warp's 96-k slice (P via in-register frags) ----
        float o[4][4] = {};
        #pragma unroll
        for (int nt = 0; nt < 12; nt++) {
            int srcA = (lane & 28) | (t >> 1);
            int srcB = srcA + 2;
            float v0A = __shfl_sync(~0u, s[nt][0], srcA);
            float v1A = __shfl_sync(~0u, s[nt][1], srcA);
            float v2A = __shfl_sync(~0u, s[nt][2], srcA);
            float v3A = __shfl_sync(~0u, s[nt][3], srcA);
            float v0B = __shfl_sync(~0u, s[nt][0], srcB);
            float v1B = __shfl_sync(~0u, s[nt][1], srcB);
            float v2B = __shfl_sync(~0u, s[nt][2], srcB);
            float v3B = __shfl_sync(~0u, s[nt][3], srcB);
            bool odd = (t & 1);
            uint32_t a[4];
            a[0] = __float_as_uint(to_tf32(odd ? v1A : v0A));
            a[1] = __float_as_uint(to_tf32(odd ? v3A : v2A));
            a[2] = __float_as_uint(to_tf32(odd ? v1B : v0B));
            a[3] = __float_as_uint(to_tf32(odd ? v3B : v2B));
            const uint32_t* vrow = (const uint32_t*)(Vs + (wn * 96 + nt * 8 + t) * VS_S);
            #pragma unroll
            for (int ntile = 0; ntile < 4; ntile++) {
                uint32_t b[2] = { vrow[ntile * 8 + g], vrow[4 * VS_S + ntile * 8 + g] };
                mma8(o[ntile], a, b);
            }
        }

        // ---- write partial o ----
        float* ob = obuf + wn * (64 * OB_S);
        #pragma unroll
        for (int ntile = 0; ntile < 4; ntile++) {
            int c = ntile * 8 + 2 * t;
            float2 e0 = { o[ntile][0], o[ntile][1] };
            *(float2*)&ob[(wm * 16 + g) * OB_S + c] = e0;
            float2 e1 = { o[ntile][2], o[ntile][3] };
            *(float2*)&ob[(wm * 16 + g + 8) * OB_S + c] = e1;
        }
        __syncthreads();

        // ---- combine: rescale partials, normalize, gate, store ----
        {
            int q = tid >> 3, c4 = (tid & 7) * 4;
            float4 lm4 = *(const float4*)&redA[q * 4];
            float4 sw4 = *(const float4*)&redB[q * 4];
            float lm[4] = { lm4.x, lm4.y, lm4.z, lm4.w };
            float sw[4] = { sw4.x, sw4.y, sw4.z, sw4.w };
            float gm = fmaxf(fmaxf(lm[0], lm[1]), fmaxf(lm[2], lm[3]));
            float total = 0.f;
            float ax = 0.f, ay = 0.f, az = 0.f, aw = 0.f;
            #pragma unroll
            for (int w = 0; w < 4; w++) {
                float e = __expf(lm[w] - gm);
                total += sw[w] * e;
                float4 pv = *(const float4*)&obuf[w * (64 * OB_S) + q * OB_S + c4];
                ax += pv.x * e; ay += pv.y * e; az += pv.z * e; aw += pv.w * e;
            }
            float inv = 1.0f / total;
            size_t idx = (size_t)(i * NSEQ + q0 + q) * CIN + h * CHD + c4;
            float4 gg = *(const float4*)&g_g[idx];
            float4 res = { ax * inv * gg.x, ay * inv * gg.y,
                           az * inv * gg.z, aw * inv * gg.w };
            *(float4*)&g_og[idx] = res;
        }
        // next pass's first __syncthreads protects obuf/redA/redB reuse
    }
}

// ============================================================
// Kernel 4: out = og @ wo. BM=64, BN=128, 2 CTAs/SM.
// ============================================================
__global__ __launch_bounds__(256, 2)
void out_tc(const float* __restrict__ wo, float* __restrict__ out) {
    extern __shared__ float sm[];
    float* As = sm;
    float* Bs = sm + 64 * AS;
    int tid = threadIdx.x, lane = tid & 31, warp = tid >> 5;
    int g = lane >> 2, t = lane & 3;
    int m0 = blockIdx.x * 64;

    const float4* Ag = (const float4*)(g_og + (size_t)m0 * CIN);
    const float4* Bg = (const float4*)wo;
    #pragma unroll
    for (int e = 0; e < 8; e++) {
        int f = tid + e * 256;
        int row = f >> 5, c4 = (f & 31) * 4;
        float4 va = Ag[f];
        As[row * AS + c4 + 0] = to_tf32(va.x); As[row * AS + c4 + 1] = to_tf32(va.y);
        As[row * AS + c4 + 2] = to_tf32(va.z); As[row * AS + c4 + 3] = to_tf32(va.w);
    }
    #pragma unroll
    for (int e = 0; e < 16; e++) {
        int f = tid + e * 256;
        int row = f >> 5, c4 = (f & 31) * 4;
        float4 vb = Bg[f];
        Bs[row * BS + c4 + 0] = to_tf32(vb.x); Bs[row * BS + c4 + 1] = to_tf32(vb.y);
        Bs[row * BS + c4 + 2] = to_tf32(vb.z); Bs[row * BS + c4 + 3] = to_tf32(vb.w);
    }
    __syncthreads();

    int wm = warp >> 2, wn = warp & 3;
    float acc[2][4][4] = {};
    #pragma unroll
    for (int kc = 0; kc < 16; kc++) {
        uint32_t a[2][4];
        #pragma unroll
        for (int mt = 0; mt < 2; mt++) {
            const uint32_t* ap = (const uint32_t*)(As + (wm * 32 + mt * 16 + g) * AS + kc * 8 + t);
            a[mt][0] = ap[0]; a[mt][1] = ap[8 * AS]; a[mt][2] = ap[4]; a[mt][3] = ap[8 * AS + 4];
        }
        #pragma unroll
        for (int nt = 0; nt < 4; nt++) {
            const uint32_t* bp = (const uint32_t*)(Bs + (kc * 8 + t) * BS + wn * 32 + nt * 8 + g);
            uint32_t b[2] = { bp[0], bp[4 * BS] };
            mma8(acc[0][nt], a[0], b);
            mma8(acc[1][nt], a[1], b);
        }
    }
    #pragma unroll
    for (int mt = 0; mt < 2; mt++)
        #pragma unroll
        for (int nt = 0; nt < 4; nt++)
            #pragma unroll
            for (int hf = 0; hf < 2; hf++) {
                int gm  = m0 + wm * 32 + mt * 16 + g + hf * 8;
                int col = wn * 32 + nt * 8 + 2 * t;
                float2 o = { acc[mt][nt][hf * 2 + 0], acc[mt][nt][hf * 2 + 1] };
                *(float2*)&out[(size_t)gm * CIN + col] = o;
            }
}

// ============================================================
extern "C" void kernel_launch(void* const* d_in, const int* in_sizes, int n_in,
                              void* d_out, int out_size) {
    const float* z     = (const float*)d_in[0];
    const float* mask  = (const float*)d_in[1];
    const float* ln_w  = (const float*)d_in[2];
    const float* ln_b  = (const float*)d_in[3];
    const float* w_tri = (const float*)d_in[4];
    const float* wq    = (const float*)d_in[5];
    const float* wk    = (const float*)d_in[6];
    const float* wv    = (const float*)d_in[7];
    const float* wg    = (const float*)d_in[8];
    const float* wo    = (const float*)d_in[9];
    float* out = (float*)d_out;

    ln_tri_kernel<<<NTOK / 8, 256>>>(z, ln_w, ln_b, w_tri);

    size_t gemm_smem = (size_t)(64 * AS + 128 * BS) * sizeof(float);  // 103424
    cudaFuncSetAttribute(proj_tc, cudaFuncAttributeMaxDynamicSharedMemorySize, (int)gemm_smem);
    cudaFuncSetAttribute(out_tc,  cudaFuncAttributeMaxDynamicSharedMemorySize, (int)gemm_smem);

    dim3 gp(4, NTOK / 64);
    proj_tc<<<gp, 256, gemm_smem>>>(wq, wk, wv, wg);

    size_t att_smem = (size_t)(NSEQ * KS_S + NSEQ * VS_S + 64 * QS_S
                               + NSEQ + 256 + 256 + 4 * 64 * OB_S) * sizeof(float);
    cudaFuncSetAttribute(attn_tc, cudaFuncAttributeMaxDynamicSharedMemorySize, (int)att_smem);
    dim3 ga(NSEQ, NH);
    attn_tc<<<ga, 512, att_smem>>>(mask);

    out_tc<<<NTOK / 64, 256, gemm_smem>>>(wo, out);
}

// round 5
// speedup vs baseline: 1.4740x; 1.4740x over previous
#include <cuda_runtime.h>
#include <math.h>
#include <stdint.h>

constexpr int NSEQ = 384;
constexpr int CIN  = 128;
constexpr int NH   = 4;
constexpr int CHD  = 32;
constexpr int NTOK = NSEQ * NSEQ;
constexpr float QSCALE = 0.17677669529663687f;

// ---- scratch ----
__device__ float g_zn[NTOK * CIN];
__device__ float g_q [NTOK * CIN];
__device__ float g_k [NTOK * CIN];
__device__ float g_v [NTOK * CIN];
__device__ float g_g [NTOK * CIN];
__device__ float g_og[NTOK * CIN];
__device__ float g_tri[NH * NTOK];   // [h][q*NSEQ+k]

__device__ __forceinline__ float to_tf32(float x) {
    float r; asm("cvt.rna.tf32.f32 %0, %1;" : "=f"(r) : "f"(x)); return r;
}
__device__ __forceinline__ void mma8(float* d, const uint32_t* a, const uint32_t* b) {
    asm volatile(
        "mma.sync.aligned.m16n8k8.row.col.f32.tf32.tf32.f32 "
        "{%0,%1,%2,%3},{%4,%5,%6,%7},{%8,%9},{%0,%1,%2,%3};"
        : "+f"(d[0]), "+f"(d[1]), "+f"(d[2]), "+f"(d[3])
        : "r"(a[0]), "r"(a[1]), "r"(a[2]), "r"(a[3]), "r"(b[0]), "r"(b[1]));
}

// ============================================================
// Kernel 1: LayerNorm + tri. 256 thr = 8 warps, warp per token.
// ============================================================
__global__ __launch_bounds__(256)
void ln_tri_kernel(const float* __restrict__ z,
                   const float* __restrict__ ln_w,
                   const float* __restrict__ ln_b,
                   const float* __restrict__ w_tri) {
    int warp = threadIdx.x >> 5, lane = threadIdx.x & 31;
    int t = blockIdx.x * 8 + warp;

    float4 x = *(const float4*)&z[(size_t)t * CIN + lane * 4];
    float v1 = x.x + x.y + x.z + x.w;
    float v2 = x.x * x.x + x.y * x.y + x.z * x.z + x.w * x.w;
    #pragma unroll
    for (int off = 16; off; off >>= 1) {
        v1 += __shfl_xor_sync(~0u, v1, off);
        v2 += __shfl_xor_sync(~0u, v2, off);
    }
    float mean = v1 * (1.0f / CIN);
    float var  = v2 * (1.0f / CIN) - mean * mean;
    float rs   = rsqrtf(var + 1e-5f);

    float4 w = *(const float4*)&ln_w[lane * 4];
    float4 b = *(const float4*)&ln_b[lane * 4];
    float4 zn;
    zn.x = (x.x - mean) * rs * w.x + b.x;
    zn.y = (x.y - mean) * rs * w.y + b.y;
    zn.z = (x.z - mean) * rs * w.z + b.z;
    zn.w = (x.w - mean) * rs * w.w + b.w;
    *(float4*)&g_zn[(size_t)t * CIN + lane * 4] = zn;

    float p[4] = {};
    float zc[4] = { zn.x, zn.y, zn.z, zn.w };
    #pragma unroll
    for (int cc = 0; cc < 4; cc++) {
        float4 wt = *(const float4*)&w_tri[(lane * 4 + cc) * NH];
        p[0] += zc[cc] * wt.x; p[1] += zc[cc] * wt.y;
        p[2] += zc[cc] * wt.z; p[3] += zc[cc] * wt.w;
    }
    #pragma unroll
    for (int off = 16; off; off >>= 1)
        #pragma unroll
        for (int h = 0; h < 4; h++) p[h] += __shfl_xor_sync(~0u, p[h], off);
    if (lane == 0)
        #pragma unroll
        for (int h = 0; h < 4; h++) g_tri[(size_t)h * NTOK + t] = p[h];
}

// ============================================================
// Kernel 2: projections. BM=64, BN=128, BK=128, 2 CTAs/SM.
// ============================================================
constexpr int AS = 132, BS = 136;

__global__ __launch_bounds__(256, 2)
void proj_tc(const float* __restrict__ wq, const float* __restrict__ wk,
             const float* __restrict__ wv, const float* __restrict__ wg) {
    extern __shared__ float sm[];
    float* As = sm;              // 64 x AS
    float* Bs = sm + 64 * AS;    // 128 x BS
    int tid = threadIdx.x, lane = tid & 31, warp = tid >> 5;
    int g = lane >> 2, t = lane & 3;
    int sel = blockIdx.x;
    const float* W = (sel == 0) ? wq : (sel == 1) ? wk : (sel == 2) ? wv : wg;
    int m0 = blockIdx.y * 64;

    const float4* Ag = (const float4*)(g_zn + (size_t)m0 * CIN);
    const float4* Bg = (const float4*)W;
    #pragma unroll
    for (int e = 0; e < 8; e++) {
        int f = tid + e * 256;
        int row = f >> 5, c4 = (f & 31) * 4;
        float4 va = Ag[f];
        As[row * AS + c4 + 0] = to_tf32(va.x); As[row * AS + c4 + 1] = to_tf32(va.y);
        As[row * AS + c4 + 2] = to_tf32(va.z); As[row * AS + c4 + 3] = to_tf32(va.w);
    }
    #pragma unroll
    for (int e = 0; e < 16; e++) {
        int f = tid + e * 256;
        int row = f >> 5, c4 = (f & 31) * 4;
        float4 vb = Bg[f];
        Bs[row * BS + c4 + 0] = to_tf32(vb.x); Bs[row * BS + c4 + 1] = to_tf32(vb.y);
        Bs[row * BS + c4 + 2] = to_tf32(vb.z); Bs[row * BS + c4 + 3] = to_tf32(vb.w);
    }
    __syncthreads();

    int wm = warp >> 2, wn = warp & 3;   // 2 x 4; warp tile 32 x 32
    float acc[2][4][4] = {};
    #pragma unroll
    for (int kc = 0; kc < 16; kc++) {
        uint32_t a[2][4];
        #pragma unroll
        for (int mt = 0; mt < 2; mt++) {
            const uint32_t* ap = (const uint32_t*)(As + (wm * 32 + mt * 16 + g) * AS + kc * 8 + t);
            a[mt][0] = ap[0]; a[mt][1] = ap[8 * AS]; a[mt][2] = ap[4]; a[mt][3] = ap[8 * AS + 4];
        }
        #pragma unroll
        for (int nt = 0; nt < 4; nt++) {
            const uint32_t* bp = (const uint32_t*)(Bs + (kc * 8 + t) * BS + wn * 32 + nt * 8 + g);
            uint32_t b[2] = { bp[0], bp[4 * BS] };
            mma8(acc[0][nt], a[0], b);
            mma8(acc[1][nt], a[1], b);
        }
    }
    #pragma unroll
    for (int mt = 0; mt < 2; mt++)
        #pragma unroll
        for (int nt = 0; nt < 4; nt++)
            #pragma unroll
            for (int hf = 0; hf < 2; hf++) {
                int gm  = m0 + wm * 32 + mt * 16 + g + hf * 8;
                int col = wn * 32 + nt * 8 + 2 * t;
                float c0 = acc[mt][nt][hf * 2 + 0], c1 = acc[mt][nt][hf * 2 + 1];
                size_t idx = (size_t)gm * CIN + col;
                if (sel == 0) {
                    float2 o = { c0 * QSCALE, c1 * QSCALE };
                    *(float2*)&g_q[idx] = o;
                } else if (sel == 1) {
                    float2 o = { c0, c1 };
                    *(float2*)&g_k[idx] = o;
                } else if (sel == 2) {
                    float2 o = { c0, c1 };
                    *(float2*)&g_v[idx] = o;
                } else {
                    float2 o = { 1.0f / (1.0f + __expf(-c0)), 1.0f / (1.0f + __expf(-c1)) };
                    *(float2*)&g_g[idx] = o;
                }
            }
}

// ============================================================
// Kernel 3: attention. 512 threads, 6 passes of 64 q rows.
// QK: 16 warps 4(M) x 4(N), warp tile 16 x 96.
// Softmax: warp-local max/sum (flash-style rescale at combine).
// P: C-frag -> A-frag via quad shuffles (no smem round trip).
// AV: per-warp over its 96-k slice, partials combined in smem.
// ============================================================
constexpr int KS_S = 36, VS_S = 40, QS_S = 36, OB_S = 36;

__global__ __launch_bounds__(512, 1)
void attn_tc(const float* __restrict__ mask) {
    int i = blockIdx.x, h = blockIdx.y;
    extern __shared__ float sm[];
    float* Ks   = sm;                       // 384*36
    float* Vs   = Ks + NSEQ * KS_S;         // 384*40
    float* Qs   = Vs + NSEQ * VS_S;         // 64*36
    float* bsm  = Qs + 64 * QS_S;           // 384
    float* redA = bsm + NSEQ;               // 64*4 local max
    float* redB = redA + 256;               // 64*4 local sum
    float* obuf = redB + 256;               // 4 * 64 * 36

    int tid = threadIdx.x, lane = tid & 31, warp = tid >> 5;
    int g = lane >> 2, t = lane & 3;
    int wm = warp & 3, wn = warp >> 2;

    // ---- load K, V (tf32) ----
    #pragma unroll
    for (int e = 0; e < 6; e++) {
        int f = tid + e * 512;                  // 3072 float4s
        int row = f >> 3, c4 = (f & 7) * 4;
        size_t src = (size_t)(i * NSEQ + row) * CIN + h * CHD + c4;
        float4 vk = *(const float4*)&g_k[src];
        Ks[row * KS_S + c4 + 0] = to_tf32(vk.x); Ks[row * KS_S + c4 + 1] = to_tf32(vk.y);
        Ks[row * KS_S + c4 + 2] = to_tf32(vk.z); Ks[row * KS_S + c4 + 3] = to_tf32(vk.w);
        float4 vv = *(const float4*)&g_v[src];
        Vs[row * VS_S + c4 + 0] = to_tf32(vv.x); Vs[row * VS_S + c4 + 1] = to_tf32(vv.y);
        Vs[row * VS_S + c4 + 2] = to_tf32(vv.z); Vs[row * VS_S + c4 + 3] = to_tf32(vv.w);
    }
    if (tid < NSEQ)
        bsm[tid] = 1e9f * (mask[i * NSEQ + tid] - 1.0f);

    const float* trih = g_tri + (size_t)h * NTOK;

    for (int pass = 0; pass < 6; pass++) {
        int q0 = pass * 64;

        // ---- fill Qs (64 x 32) ----
        {
            int row = tid >> 3, c4 = (tid & 7) * 4;
            size_t src = (size_t)(i * NSEQ + q0 + row) * CIN + h * CHD + c4;
            float4 v = *(const float4*)&g_q[src];
            Qs[row * QS_S + c4 + 0] = to_tf32(v.x); Qs[row * QS_S + c4 + 1] = to_tf32(v.y);
            Qs[row * QS_S + c4 + 2] = to_tf32(v.z); Qs[row * QS_S + c4 + 3] = to_tf32(v.w);
        }
        __syncthreads();   // Qs ready (and, for pass 0, K/V/bsm; later: obuf reuse)

        // ---- QK: S[16 x 96] per warp ----
        float s[12][4] = {};
        #pragma unroll
        for (int kc = 0; kc < 4; kc++) {
            const uint32_t* ap = (const uint32_t*)(Qs + (wm * 16 + g) * QS_S + kc * 8 + t);
            uint32_t a[4] = { ap[0], ap[8 * QS_S], ap[4], ap[8 * QS_S + 4] };
            #pragma unroll
            for (int nt = 0; nt < 12; nt++) {
                const uint32_t* bp = (const uint32_t*)(Ks + (wn * 96 + nt * 8 + g) * KS_S + kc * 8 + t);
                uint32_t b[2] = { bp[0], bp[4] };
                mma8(s[nt], a, b);
            }
        }

        // ---- biases + warp-local row max ----
        int qa = q0 + wm * 16 + g, qb = qa + 8;
        float rm0 = -1e30f, rm1 = -1e30f;
        #pragma unroll
        for (int nt = 0; nt < 12; nt++) {
            int k = wn * 96 + nt * 8 + 2 * t;
            float b0 = bsm[k], b1 = bsm[k + 1];
            float2 t0 = *(const float2*)&trih[(size_t)qa * NSEQ + k];
            float2 t1 = *(const float2*)&trih[(size_t)qb * NSEQ + k];
            s[nt][0] += b0 + t0.x; s[nt][1] += b1 + t0.y;
            s[nt][2] += b0 + t1.x; s[nt][3] += b1 + t1.y;
            rm0 = fmaxf(rm0, fmaxf(s[nt][0], s[nt][1]));
            rm1 = fmaxf(rm1, fmaxf(s[nt][2], s[nt][3]));
        }
        rm0 = fmaxf(rm0, __shfl_xor_sync(~0u, rm0, 1));
        rm0 = fmaxf(rm0, __shfl_xor_sync(~0u, rm0, 2));
        rm1 = fmaxf(rm1, __shfl_xor_sync(~0u, rm1, 1));
        rm1 = fmaxf(rm1, __shfl_xor_sync(~0u, rm1, 2));

        // ---- exp (local max) + warp-local sums ----
        float sum0 = 0.f, sum1 = 0.f;
        #pragma unroll
        for (int nt = 0; nt < 12; nt++) {
            s[nt][0] = __expf(s[nt][0] - rm0); sum0 += s[nt][0];
            s[nt][1] = __expf(s[nt][1] - rm0); sum0 += s[nt][1];
            s[nt][2] = __expf(s[nt][2] - rm1); sum1 += s[nt][2];
            s[nt][3] = __expf(s[nt][3] - rm1); sum1 += s[nt][3];
        }
        sum0 += __shfl_xor_sync(~0u, sum0, 1); sum0 += __shfl_xor_sync(~0u, sum0, 2);
        sum1 += __shfl_xor_sync(~0u, sum1, 1); sum1 += __shfl_xor_sync(~0u, sum1, 2);
        if (t == 0) {
            redA[(wm * 16 + g) * 4 + wn]     = rm0;
            redA[(wm * 16 + g + 8) * 4 + wn] = rm1;
            redB[(wm * 16 + g) * 4 + wn]     = sum0;
            redB[(wm * 16 + g + 8) * 4 + wn] = sum1;
        }

        // ---- AV over this warp's 96-k slice (P via in-register frags) ----
        float o[4][4] = {};
        #pragma unroll
        for (int nt = 0; nt < 12; nt++) {
            int srcA = (lane & 28) | (t >> 1);
            int srcB = srcA + 2;
            float v0A = __shfl_sync(~0u, s[nt][0], srcA);
            float v1A = __shfl_sync(~0u, s[nt][1], srcA);
            float v2A = __shfl_sync(~0u, s[nt][2], srcA);
            float v3A = __shfl_sync(~0u, s[nt][3], srcA);
            float v0B = __shfl_sync(~0u, s[nt][0], srcB);
            float v1B = __shfl_sync(~0u, s[nt][1], srcB);
            float v2B = __shfl_sync(~0u, s[nt][2], srcB);
            float v3B = __shfl_sync(~0u, s[nt][3], srcB);
            bool odd = (t & 1);
            uint32_t a[4];
            a[0] = __float_as_uint(to_tf32(odd ? v1A : v0A));
            a[1] = __float_as_uint(to_tf32(odd ? v3A : v2A));
            a[2] = __float_as_uint(to_tf32(odd ? v1B : v0B));
            a[3] = __float_as_uint(to_tf32(odd ? v3B : v2B));
            const uint32_t* vrow = (const uint32_t*)(Vs + (wn * 96 + nt * 8 + t) * VS_S);
            #pragma unroll
            for (int ntile = 0; ntile < 4; ntile++) {
                uint32_t b[2] = { vrow[ntile * 8 + g], vrow[4 * VS_S + ntile * 8 + g] };
                mma8(o[ntile], a, b);
            }
        }

        // ---- write partial o ----
        float* ob = obuf + wn * (64 * OB_S);
        #pragma unroll
        for (int ntile = 0; ntile < 4; ntile++) {
            int c = ntile * 8 + 2 * t;
            float2 e0 = { o[ntile][0], o[ntile][1] };
            *(float2*)&ob[(wm * 16 + g) * OB_S + c] = e0;
            float2 e1 = { o[ntile][2], o[ntile][3] };
            *(float2*)&ob[(wm * 16 + g + 8) * OB_S + c] = e1;
        }
        __syncthreads();

        // ---- combine: rescale partials, normalize, gate, store ----
        {
            int q = tid >> 3, c4 = (tid & 7) * 4;
            float4 lm4 = *(const float4*)&redA[q * 4];
            float4 sw4 = *(const float4*)&redB[q * 4];
            float lm[4] = { lm4.x, lm4.y, lm4.z, lm4.w };
            float sw[4] = { sw4.x, sw4.y, sw4.z, sw4.w };
            float gm = fmaxf(fmaxf(lm[0], lm[1]), fmaxf(lm[2], lm[3]));
            float total = 0.f;
            float ax = 0.f, ay = 0.f, az = 0.f, aw = 0.f;
            #pragma unroll
            for (int w = 0; w < 4; w++) {
                float e = __expf(lm[w] - gm);
                total += sw[w] * e;
                float4 pv = *(const float4*)&obuf[w * (64 * OB_S) + q * OB_S + c4];
                ax += pv.x * e; ay += pv.y * e; az += pv.z * e; aw += pv.w * e;
            }
            float inv = 1.0f / total;
            size_t idx = (size_t)(i * NSEQ + q0 + q) * CIN + h * CHD + c4;
            float4 gg = *(const float4*)&g_g[idx];
            float4 res = { ax * inv * gg.x, ay * inv * gg.y,
                           az * inv * gg.z, aw * inv * gg.w };
            *(float4*)&g_og[idx] = res;
        }
        // next pass's first __syncthreads protects obuf/redA/redB reuse
    }
}

// ============================================================
// Kernel 4: out = og @ wo. BM=64, BN=128, 2 CTAs/SM.
// ============================================================
__global__ __launch_bounds__(256, 2)
void out_tc(const float* __restrict__ wo, float* __restrict__ out) {
    extern __shared__ float sm[];
    float* As = sm;
    float* Bs = sm + 64 * AS;
    int tid = threadIdx.x, lane = tid & 31, warp = tid >> 5;
    int g = lane >> 2, t = lane & 3;
    int m0 = blockIdx.x * 64;

    const float4* Ag = (const float4*)(g_og + (size_t)m0 * CIN);
    const float4* Bg = (const float4*)wo;
    #pragma unroll
    for (int e = 0; e < 8; e++) {
        int f = tid + e * 256;
        int row = f >> 5, c4 = (f & 31) * 4;
        float4 va = Ag[f];
        As[row * AS + c4 + 0] = to_tf32(va.x); As[row * AS + c4 + 1] = to_tf32(va.y);
        As[row * AS + c4 + 2] = to_tf32(va.z); As[row * AS + c4 + 3] = to_tf32(va.w);
    }
    #pragma unroll
    for (int e = 0; e < 16; e++) {
        int f = tid + e * 256;
        int row = f >> 5, c4 = (f & 31) * 4;
        float4 vb = Bg[f];
        Bs[row * BS + c4 + 0] = to_tf32(vb.x); Bs[row * BS + c4 + 1] = to_tf32(vb.y);
        Bs[row * BS + c4 + 2] = to_tf32(vb.z); Bs[row * BS + c4 + 3] = to_tf32(vb.w);
    }
    __syncthreads();

    int wm = warp >> 2, wn = warp & 3;
    float acc[2][4][4] = {};
    #pragma unroll
    for (int kc = 0; kc < 16; kc++) {
        uint32_t a[2][4];
        #pragma unroll
        for (int mt = 0; mt < 2; mt++) {
            const uint32_t* ap = (const uint32_t*)(As + (wm * 32 + mt * 16 + g) * AS + kc * 8 + t);
            a[mt][0] = ap[0]; a[mt][1] = ap[8 * AS]; a[mt][2] = ap[4]; a[mt][3] = ap[8 * AS + 4];
        }
        #pragma unroll
        for (int nt = 0; nt < 4; nt++) {
            const uint32_t* bp = (const uint32_t*)(Bs + (kc * 8 + t) * BS + wn * 32 + nt * 8 + g);
            uint32_t b[2] = { bp[0], bp[4 * BS] };
            mma8(acc[0][nt], a[0], b);
            mma8(acc[1][nt], a[1], b);
        }
    }
    #pragma unroll
    for (int mt = 0; mt < 2; mt++)
        #pragma unroll
        for (int nt = 0; nt < 4; nt++)
            #pragma unroll
            for (int hf = 0; hf < 2; hf++) {
                int gm  = m0 + wm * 32 + mt * 16 + g + hf * 8;
                int col = wn * 32 + nt * 8 + 2 * t;
                float2 o = { acc[mt][nt][hf * 2 + 0], acc[mt][nt][hf * 2 + 1] };
                *(float2*)&out[(size_t)gm * CIN + col] = o;
            }
}

// ============================================================
extern "C" void kernel_launch(void* const* d_in, const int* in_sizes, int n_in,
                              void* d_out, int out_size) {
    const float* z     = (const float*)d_in[0];
    const float* mask  = (const float*)d_in[1];
    const float* ln_w  = (const float*)d_in[2];
    const float* ln_b  = (const float*)d_in[3];
    const float* w_tri = (const float*)d_in[4];
    const float* wq    = (const float*)d_in[5];
    const float* wk    = (const float*)d_in[6];
    const float* wv    = (const float*)d_in[7];
    const float* wg    = (const float*)d_in[8];
    const float* wo    = (const float*)d_in[9];
    float* out = (float*)d_out;

    ln_tri_kernel<<<NTOK / 8, 256>>>(z, ln_w, ln_b, w_tri);

    size_t gemm_smem = (size_t)(64 * AS + 128 * BS) * sizeof(float);  // 103424
    cudaFuncSetAttribute(proj_tc, cudaFuncAttributeMaxDynamicSharedMemorySize, (int)gemm_smem);
    cudaFuncSetAttribute(out_tc,  cudaFuncAttributeMaxDynamicSharedMemorySize, (int)gemm_smem);

    dim3 gp(4, NTOK / 64);
    proj_tc<<<gp, 256, gemm_smem>>>(wq, wk, wv, wg);

    size_t att_smem = (size_t)(NSEQ * KS_S + NSEQ * VS_S + 64 * QS_S
                               + NSEQ + 256 + 256 + 4 * 64 * OB_S) * sizeof(float);
    cudaFuncSetAttribute(attn_tc, cudaFuncAttributeMaxDynamicSharedMemorySize, (int)att_smem);
    dim3 ga(NSEQ, NH);
    attn_tc<<<ga, 512, att_smem>>>(mask);

    out_tc<<<NTOK / 64, 256, gemm_smem>>>(wo, out);
}

// round 6
// speedup vs baseline: 2.5735x; 1.7460x over previous
#include <cuda_runtime.h>
#include <cuda_fp16.h>
#include <math.h>
#include <stdint.h>

constexpr int NSEQ = 384;
constexpr int CIN  = 128;
constexpr int NH   = 4;
constexpr int CHD  = 32;
constexpr int NTOK = NSEQ * NSEQ;
constexpr float QSCALE = 0.17677669529663687f;

// ---- scratch ----
__device__ __half g_znh[NTOK * CIN];
__device__ __half g_qh [NTOK * CIN];
__device__ __half g_kh [NTOK * CIN];
__device__ __half g_vh [NTOK * CIN];
__device__ float  g_g  [NTOK * CIN];
__device__ float  g_og [NTOK * CIN];
__device__ float  g_tri[NH * NTOK];   // [h][q*NSEQ+k]

__device__ __forceinline__ uint32_t h2u(__half2 h) { return *(uint32_t*)&h; }

__device__ __forceinline__ void ldm_x4(uint32_t* r, const void* p) {
    uint32_t a = (uint32_t)__cvta_generic_to_shared(p);
    asm volatile("ldmatrix.sync.aligned.m8n8.x4.shared.b16 {%0,%1,%2,%3}, [%4];"
        : "=r"(r[0]), "=r"(r[1]), "=r"(r[2]), "=r"(r[3]) : "r"(a));
}
__device__ __forceinline__ void ldm_x4t(uint32_t* r, const void* p) {
    uint32_t a = (uint32_t)__cvta_generic_to_shared(p);
    asm volatile("ldmatrix.sync.aligned.m8n8.x4.trans.shared.b16 {%0,%1,%2,%3}, [%4];"
        : "=r"(r[0]), "=r"(r[1]), "=r"(r[2]), "=r"(r[3]) : "r"(a));
}
__device__ __forceinline__ void ldm_x2t(uint32_t* r, const void* p) {
    uint32_t a = (uint32_t)__cvta_generic_to_shared(p);
    asm volatile("ldmatrix.sync.aligned.m8n8.x2.trans.shared.b16 {%0,%1}, [%2];"
        : "=r"(r[0]), "=r"(r[1]) : "r"(a));
}
// D += A(16x16) * B(16x8), fp16 in, fp32 accum
__device__ __forceinline__ void mma16(float* d, const uint32_t* a, const uint32_t* b) {
    asm volatile(
        "mma.sync.aligned.m16n8k16.row.col.f32.f16.f16.f32 "
        "{%0,%1,%2,%3},{%4,%5,%6,%7},{%8,%9},{%0,%1,%2,%3};"
        : "+f"(d[0]), "+f"(d[1]), "+f"(d[2]), "+f"(d[3])
        : "r"(a[0]), "r"(a[1]), "r"(a[2]), "r"(a[3]), "r"(b[0]), "r"(b[1]));
}

// ============================================================
// Kernel 1: LayerNorm + tri. Warp per token. zn stored half.
// ============================================================
__global__ __launch_bounds__(256)
void ln_tri_kernel(const float* __restrict__ z,
                   const float* __restrict__ ln_w,
                   const float* __restrict__ ln_b,
                   const float* __restrict__ w_tri) {
    int warp = threadIdx.x >> 5, lane = threadIdx.x & 31;
    int t = blockIdx.x * 8 + warp;

    float4 x = *(const float4*)&z[(size_t)t * CIN + lane * 4];
    float v1 = x.x + x.y + x.z + x.w;
    float v2 = x.x * x.x + x.y * x.y + x.z * x.z + x.w * x.w;
    #pragma unroll
    for (int off = 16; off; off >>= 1) {
        v1 += __shfl_xor_sync(~0u, v1, off);
        v2 += __shfl_xor_sync(~0u, v2, off);
    }
    float mean = v1 * (1.0f / CIN);
    float var  = v2 * (1.0f / CIN) - mean * mean;
    float rs   = rsqrtf(var + 1e-5f);

    float4 w = *(const float4*)&ln_w[lane * 4];
    float4 b = *(const float4*)&ln_b[lane * 4];
    float4 zn;
    zn.x = (x.x - mean) * rs * w.x + b.x;
    zn.y = (x.y - mean) * rs * w.y + b.y;
    zn.z = (x.z - mean) * rs * w.z + b.z;
    zn.w = (x.w - mean) * rs * w.w + b.w;
    uint2 u = { h2u(__floats2half2_rn(zn.x, zn.y)), h2u(__floats2half2_rn(zn.z, zn.w)) };
    *(uint2*)&g_znh[(size_t)t * CIN + lane * 4] = u;

    float p[4] = {};
    float zc[4] = { zn.x, zn.y, zn.z, zn.w };
    #pragma unroll
    for (int cc = 0; cc < 4; cc++) {
        float4 wt = *(const float4*)&w_tri[(lane * 4 + cc) * NH];
        p[0] += zc[cc] * wt.x; p[1] += zc[cc] * wt.y;
        p[2] += zc[cc] * wt.z; p[3] += zc[cc] * wt.w;
    }
    #pragma unroll
    for (int off = 16; off; off >>= 1)
        #pragma unroll
        for (int h = 0; h < 4; h++) p[h] += __shfl_xor_sync(~0u, p[h], off);
    if (lane == 0)
        #pragma unroll
        for (int h = 0; h < 4; h++) g_tri[(size_t)h * NTOK + t] = p[h];
}

// ============================================================
// Kernel 2: projections, fp16 mma. BM=128,BN=128,BK=128.
// As[m][c] halves (stride 136), Bs[c][n] halves (natural W,
// stride 136); A frags ldmatrix.x4, B frags ldmatrix.x4.trans.
// ============================================================
constexpr int HS = 136;   // halves per smem row

__global__ __launch_bounds__(256, 2)
void proj_tc(const float* __restrict__ wq, const float* __restrict__ wk,
             const float* __restrict__ wv, const float* __restrict__ wg) {
    extern __shared__ __half smh[];
    __half* As = smh;                 // 128 x HS
    __half* Bs = smh + 128 * HS;      // 128 x HS
    int tid = threadIdx.x, lane = tid & 31, warp = tid >> 5;
    int g = lane >> 2, t = lane & 3;
    int sel = blockIdx.x;
    const float* W = (sel == 0) ? wq : (sel == 1) ? wk : (sel == 2) ? wv : wg;
    int m0 = blockIdx.y * 128;

    #pragma unroll
    for (int e = 0; e < 8; e++) {       // A: 2048 uint4
        int f = tid + e * 256;
        int row = f >> 4, c8 = (f & 15) * 8;
        *(uint4*)&As[row * HS + c8] = *(const uint4*)&g_znh[(size_t)(m0 + row) * CIN + c8];
    }
    #pragma unroll
    for (int e = 0; e < 16; e++) {      // B: 4096 float4 -> half
        int f = tid + e * 256;
        int row = f >> 5, c4 = (f & 31) * 4;
        float4 v = *(const float4*)&W[(size_t)row * CIN + c4];
        uint2 u = { h2u(__floats2half2_rn(v.x, v.y)), h2u(__floats2half2_rn(v.z, v.w)) };
        *(uint2*)&Bs[row * HS + c4] = u;
    }
    __syncthreads();

    int wm = warp >> 1, wn = warp & 1;   // 4x2, warp tile 32m x 64n
    float acc[2][8][4] = {};
    #pragma unroll
    for (int kc2 = 0; kc2 < 4; kc2++) {  // 32 c per iter
        uint32_t bf[8][4];
        #pragma unroll
        for (int nt = 0; nt < 8; nt++)
            ldm_x4t(bf[nt], &Bs[(kc2 * 32 + lane) * HS + wn * 64 + nt * 8]);
        #pragma unroll
        for (int kk = 0; kk < 2; kk++) {
            uint32_t af[2][4];
            #pragma unroll
            for (int mt = 0; mt < 2; mt++)
                ldm_x4(af[mt], &As[(wm * 32 + mt * 16 + (lane & 15)) * HS
                                   + (kc2 * 2 + kk) * 16 + (lane >> 4) * 8]);
            #pragma unroll
            for (int nt = 0; nt < 8; nt++) {
                mma16(acc[0][nt], af[0], &bf[nt][kk * 2]);
                mma16(acc[1][nt], af[1], &bf[nt][kk * 2]);
            }
        }
    }
    #pragma unroll
    for (int mt = 0; mt < 2; mt++)
        #pragma unroll
        for (int nt = 0; nt < 8; nt++)
            #pragma unroll
            for (int hf = 0; hf < 2; hf++) {
                int gm  = m0 + wm * 32 + mt * 16 + g + hf * 8;
                int col = wn * 64 + nt * 8 + 2 * t;
                float c0 = acc[mt][nt][hf * 2 + 0], c1 = acc[mt][nt][hf * 2 + 1];
                size_t idx = (size_t)gm * CIN + col;
                if (sel == 0)
                    *(uint32_t*)&g_qh[idx] = h2u(__floats2half2_rn(c0 * QSCALE, c1 * QSCALE));
                else if (sel == 1)
                    *(uint32_t*)&g_kh[idx] = h2u(__floats2half2_rn(c0, c1));
                else if (sel == 2)
                    *(uint32_t*)&g_vh[idx] = h2u(__floats2half2_rn(c0, c1));
                else {
                    float2 o = { 1.0f / (1.0f + __expf(-c0)), 1.0f / (1.0f + __expf(-c1)) };
                    *(float2*)&g_g[idx] = o;
                }
            }
}

// ============================================================
// Kernel 3: attention, fp16 mma, warp-autonomous flash tiles.
// 256 thr, 2 blocks/SM. Warp tile 16q x 384k, 4 chunks of 96k,
// online softmax. Zero barriers after K/V fill. P C-frag ->
// A-frag = pure register packs.
// ============================================================
constexpr int KSS = 40;   // halves per K/V row

__global__ __launch_bounds__(256, 2)
void attn_tc(const float* __restrict__ mask) {
    int i = blockIdx.x, h = blockIdx.y;
    extern __shared__ __half smh[];
    __half* Ks  = smh;                  // 384 x 40
    __half* Vs  = smh + NSEQ * KSS;     // 384 x 40
    float*  bsm = (float*)(smh + 2 * NSEQ * KSS);  // 384

    int tid = threadIdx.x, lane = tid & 31, warp = tid >> 5;
    int g = lane >> 2, t = lane & 3;

    const __half* gK = g_kh + (size_t)(i * NSEQ) * CIN + h * CHD;
    const __half* gV = g_vh + (size_t)(i * NSEQ) * CIN + h * CHD;
    #pragma unroll
    for (int e = 0; e < 12; e++) {
        int f = tid + e * 256;              // 3072 4-half units
        int row = f >> 3, c4 = (f & 7) * 4;
        *(uint2*)&Ks[row * KSS + c4] = *(const uint2*)&gK[(size_t)row * CIN + c4];
        *(uint2*)&Vs[row * KSS + c4] = *(const uint2*)&gV[(size_t)row * CIN + c4];
    }
    {
        int k = tid; // 256 threads cover 384 in 2 strides
        if (k < NSEQ) bsm[k] = 1e9f * (mask[i * NSEQ + k] - 1.0f);
        k += 256;
        if (k < NSEQ) bsm[k] = 1e9f * (mask[i * NSEQ + k] - 1.0f);
    }
    __syncthreads();

    const float* trih = g_tri + (size_t)h * NTOK;

    for (int tile = warp; tile < 24; tile += 8) {
        int q0 = tile * 16;

        // Q fragments from global (half)
        const __half* gQ = g_qh + (size_t)(i * NSEQ + q0) * CIN + h * CHD;
        uint32_t qa_[2][4];
        #pragma unroll
        for (int kc = 0; kc < 2; kc++) {
            qa_[kc][0] = *(const uint32_t*)&gQ[(size_t)g * CIN + kc * 16 + 2 * t];
            qa_[kc][1] = *(const uint32_t*)&gQ[(size_t)(g + 8) * CIN + kc * 16 + 2 * t];
            qa_[kc][2] = *(const uint32_t*)&gQ[(size_t)g * CIN + kc * 16 + 2 * t + 8];
            qa_[kc][3] = *(const uint32_t*)&gQ[(size_t)(g + 8) * CIN + kc * 16 + 2 * t + 8];
        }

        float M0 = -1e30f, M1 = -1e30f, l0 = 0.f, l1 = 0.f;
        float O[4][4] = {};

        #pragma unroll
        for (int ch = 0; ch < 4; ch++) {
            int k0c = ch * 96;

            // ---- QK scores for this 96-k chunk ----
            float s[12][4];
            #pragma unroll
            for (int nt = 0; nt < 12; nt++) {
                s[nt][0] = s[nt][1] = s[nt][2] = s[nt][3] = 0.f;
                uint32_t bf[4];
                ldm_x4(bf, &Ks[(k0c + nt * 8 + (lane & 7)) * KSS + (lane >> 3) * 8]);
                mma16(s[nt], qa_[0], &bf[0]);
                mma16(s[nt], qa_[1], &bf[2]);
            }

            // ---- biases + chunk max ----
            int qa = q0 + g, qb = qa + 8;
            float cm0 = -1e30f, cm1 = -1e30f;
            #pragma unroll
            for (int nt = 0; nt < 12; nt++) {
                int k = k0c + nt * 8 + 2 * t;
                float2 bb = *(const float2*)&bsm[k];
                float2 t0 = *(const float2*)&trih[(size_t)qa * NSEQ + k];
                float2 t1 = *(const float2*)&trih[(size_t)qb * NSEQ + k];
                s[nt][0] += bb.x + t0.x; s[nt][1] += bb.y + t0.y;
                s[nt][2] += bb.x + t1.x; s[nt][3] += bb.y + t1.y;
                cm0 = fmaxf(cm0, fmaxf(s[nt][0], s[nt][1]));
                cm1 = fmaxf(cm1, fmaxf(s[nt][2], s[nt][3]));
            }
            cm0 = fmaxf(cm0, __shfl_xor_sync(~0u, cm0, 1));
            cm0 = fmaxf(cm0, __shfl_xor_sync(~0u, cm0, 2));
            cm1 = fmaxf(cm1, __shfl_xor_sync(~0u, cm1, 1));
            cm1 = fmaxf(cm1, __shfl_xor_sync(~0u, cm1, 2));

            // ---- online rescale ----
            float Mn0 = fmaxf(M0, cm0), Mn1 = fmaxf(M1, cm1);
            float al0 = __expf(M0 - Mn0), al1 = __expf(M1 - Mn1);
            M0 = Mn0; M1 = Mn1;
            l0 *= al0; l1 *= al1;
            #pragma unroll
            for (int ct = 0; ct < 4; ct++) {
                O[ct][0] *= al0; O[ct][1] *= al0;
                O[ct][2] *= al1; O[ct][3] *= al1;
            }

            // ---- exp + chunk sums ----
            float cs0 = 0.f, cs1 = 0.f;
            #pragma unroll
            for (int nt = 0; nt < 12; nt++) {
                s[nt][0] = __expf(s[nt][0] - M0); cs0 += s[nt][0];
                s[nt][1] = __expf(s[nt][1] - M0); cs0 += s[nt][1];
                s[nt][2] = __expf(s[nt][2] - M1); cs1 += s[nt][2];
                s[nt][3] = __expf(s[nt][3] - M1); cs1 += s[nt][3];
            }
            cs0 += __shfl_xor_sync(~0u, cs0, 1); cs0 += __shfl_xor_sync(~0u, cs0, 2);
            cs1 += __shfl_xor_sync(~0u, cs1, 1); cs1 += __shfl_xor_sync(~0u, cs1, 2);
            l0 += cs0; l1 += cs1;

            // ---- AV: P A-frags are pure packs of this thread's s ----
            #pragma unroll
            for (int j = 0; j < 6; j++) {       // k16 steps
                uint32_t pa[4];
                pa[0] = h2u(__floats2half2_rn(s[2 * j][0],     s[2 * j][1]));
                pa[1] = h2u(__floats2half2_rn(s[2 * j][2],     s[2 * j][3]));
                pa[2] = h2u(__floats2half2_rn(s[2 * j + 1][0], s[2 * j + 1][1]));
                pa[3] = h2u(__floats2half2_rn(s[2 * j + 1][2], s[2 * j + 1][3]));
                #pragma unroll
                for (int ct = 0; ct < 4; ct++) {
                    uint32_t vb[2];
                    ldm_x2t(vb, &Vs[(k0c + j * 16 + (lane & 15)) * KSS + ct * 8]);
                    mma16(O[ct], pa, vb);
                }
            }
        }

        // ---- normalize, gate, store ----
        float inv0 = 1.0f / l0, inv1 = 1.0f / l1;
        #pragma unroll
        for (int ct = 0; ct < 4; ct++) {
            int c = ct * 8 + 2 * t;
            size_t idx0 = (size_t)(i * NSEQ + q0 + g) * CIN + h * CHD + c;
            size_t idx1 = idx0 + (size_t)8 * CIN;
            float2 gg0 = *(const float2*)&g_g[idx0];
            float2 gg1 = *(const float2*)&g_g[idx1];
            float2 w0 = { O[ct][0] * inv0 * gg0.x, O[ct][1] * inv0 * gg0.y };
            float2 w1 = { O[ct][2] * inv1 * gg1.x, O[ct][3] * inv1 * gg1.y };
            *(float2*)&g_og[idx0] = w0;
            *(float2*)&g_og[idx1] = w1;
        }
    }
}

// ============================================================
// Kernel 4: out = og @ wo, fp16 mma, BM=128,BN=128.
// ============================================================
__global__ __launch_bounds__(256, 2)
void out_tc(const float* __restrict__ wo, float* __restrict__ out) {
    extern __shared__ __half smh[];
    __half* As = smh;
    __half* Bs = smh + 128 * HS;
    int tid = threadIdx.x, lane = tid & 31, warp = tid >> 5;
    int g = lane >> 2, t = lane & 3;
    int m0 = blockIdx.x * 128;

    #pragma unroll
    for (int e = 0; e < 16; e++) {
        int f = tid + e * 256;
        int row = f >> 5, c4 = (f & 31) * 4;
        float4 va = *(const float4*)&g_og[(size_t)(m0 + row) * CIN + c4];
        uint2 ua = { h2u(__floats2half2_rn(va.x, va.y)), h2u(__floats2half2_rn(va.z, va.w)) };
        *(uint2*)&As[row * HS + c4] = ua;
        float4 vb = *(const float4*)&wo[(size_t)row * CIN + c4];
        uint2 ub = { h2u(__floats2half2_rn(vb.x, vb.y)), h2u(__floats2half2_rn(vb.z, vb.w)) };
        *(uint2*)&Bs[row * HS + c4] = ub;
    }
    __syncthreads();

    int wm = warp >> 1, wn = warp & 1;
    float acc[2][8][4] = {};
    #pragma unroll
    for (int kc2 = 0; kc2 < 4; kc2++) {
        uint32_t bf[8][4];
        #pragma unroll
        for (int nt = 0; nt < 8; nt++)
            ldm_x4t(bf[nt], &Bs[(kc2 * 32 + lane) * HS + wn * 64 + nt * 8]);
        #pragma unroll
        for (int kk = 0; kk < 2; kk++) {
            uint32_t af[2][4];
            #pragma unroll
            for (int mt = 0; mt < 2; mt++)
                ldm_x4(af[mt], &As[(wm * 32 + mt * 16 + (lane & 15)) * HS
                                   + (kc2 * 2 + kk) * 16 + (lane >> 4) * 8]);
            #pragma unroll
            for (int nt = 0; nt < 8; nt++) {
                mma16(acc[0][nt], af[0], &bf[nt][kk * 2]);
                mma16(acc[1][nt], af[1], &bf[nt][kk * 2]);
            }
        }
    }
    #pragma unroll
    for (int mt = 0; mt < 2; mt++)
        #pragma unroll
        for (int nt = 0; nt < 8; nt++)
            #pragma unroll
            for (int hf = 0; hf < 2; hf++) {
                int gm  = m0 + wm * 32 + mt * 16 + g + hf * 8;
                int col = wn * 64 + nt * 8 + 2 * t;
                float2 o = { acc[mt][nt][hf * 2 + 0], acc[mt][nt][hf * 2 + 1] };
                *(float2*)&out[(size_t)gm * CIN + col] = o;
            }
}

// ============================================================
extern "C" void kernel_launch(void* const* d_in, const int* in_sizes, int n_in,
                              void* d_out, int out_size) {
    const float* z     = (const float*)d_in[0];
    const float* mask  = (const float*)d_in[1];
    const float* ln_w  = (const float*)d_in[2];
    const float* ln_b  = (const float*)d_in[3];
    const float* w_tri = (const float*)d_in[4];
    const float* wq    = (const float*)d_in[5];
    const float* wk    = (const float*)d_in[6];
    const float* wv    = (const float*)d_in[7];
    const float* wg    = (const float*)d_in[8];
    const float* wo    = (const float*)d_in[9];
    float* out = (float*)d_out;

    ln_tri_kernel<<<NTOK / 8, 256>>>(z, ln_w, ln_b, w_tri);

    size_t gemm_smem = (size_t)(2 * 128 * HS) * sizeof(__half);  // 69632
    cudaFuncSetAttribute(proj_tc, cudaFuncAttributeMaxDynamicSharedMemorySize, (int)gemm_smem);
    cudaFuncSetAttribute(out_tc,  cudaFuncAttributeMaxDynamicSharedMemorySize, (int)gemm_smem);

    dim3 gp(4, NTOK / 128);
    proj_tc<<<gp, 256, gemm_smem>>>(wq, wk, wv, wg);

    size_t att_smem = (size_t)(2 * NSEQ * KSS) * sizeof(__half) + NSEQ * sizeof(float); // 62976
    cudaFuncSetAttribute(attn_tc, cudaFuncAttributeMaxDynamicSharedMemorySize, (int)att_smem);
    dim3 ga(NSEQ, NH);
    attn_tc<<<ga, 256, att_smem>>>(mask);

    out_tc<<<NTOK / 128, 256, gemm_smem>>>(wo, out);
}

// round 7
// speedup vs baseline: 2.7072x; 1.0519x over previous
#include <cuda_runtime.h>
#include <cuda_fp16.h>
#include <math.h>
#include <stdint.h>

constexpr int NSEQ = 384;
constexpr int CIN  = 128;
constexpr int NH   = 4;
constexpr int CHD  = 32;
constexpr int NTOK = NSEQ * NSEQ;
constexpr float QSCALE = 0.17677669529663687f;  // 1/sqrt(32)
constexpr float LOG2E  = 1.4426950408889634f;

// ---- scratch ----
__device__ __half g_znh[NTOK * CIN];
__device__ __half g_qh [NTOK * CIN];   // pre-scaled by QSCALE*LOG2E
__device__ __half g_kh [NTOK * CIN];
__device__ __half g_vh [NTOK * CIN];
__device__ __half g_gh [NTOK * CIN];
__device__ __half g_ogh[NTOK * CIN];
__device__ __half g_trih[NH * NTOK];   // [h][q*NSEQ+k], pre-scaled by LOG2E

__device__ __forceinline__ uint32_t h2u(__half2 h) { return *(uint32_t*)&h; }
__device__ __forceinline__ float fexp2(float x) {
    float r; asm("ex2.approx.f32 %0, %1;" : "=f"(r) : "f"(x)); return r;
}

__device__ __forceinline__ void ldm_x4(uint32_t* r, const void* p) {
    uint32_t a = (uint32_t)__cvta_generic_to_shared(p);
    asm volatile("ldmatrix.sync.aligned.m8n8.x4.shared.b16 {%0,%1,%2,%3}, [%4];"
        : "=r"(r[0]), "=r"(r[1]), "=r"(r[2]), "=r"(r[3]) : "r"(a));
}
__device__ __forceinline__ void ldm_x4t(uint32_t* r, const void* p) {
    uint32_t a = (uint32_t)__cvta_generic_to_shared(p);
    asm volatile("ldmatrix.sync.aligned.m8n8.x4.trans.shared.b16 {%0,%1,%2,%3}, [%4];"
        : "=r"(r[0]), "=r"(r[1]), "=r"(r[2]), "=r"(r[3]) : "r"(a));
}
// D += A(16x16) * B(16x8), fp16 in, fp32 accum
__device__ __forceinline__ void mma16(float* d, const uint32_t* a, const uint32_t* b) {
    asm volatile(
        "mma.sync.aligned.m16n8k16.row.col.f32.f16.f16.f32 "
        "{%0,%1,%2,%3},{%4,%5,%6,%7},{%8,%9},{%0,%1,%2,%3};"
        : "+f"(d[0]), "+f"(d[1]), "+f"(d[2]), "+f"(d[3])
        : "r"(a[0]), "r"(a[1]), "r"(a[2]), "r"(a[3]), "r"(b[0]), "r"(b[1]));
}

// ============================================================
// Kernel 1: LayerNorm + tri. Warp per token.
// ============================================================
__global__ __launch_bounds__(256)
void ln_tri_kernel(const float* __restrict__ z,
                   const float* __restrict__ ln_w,
                   const float* __restrict__ ln_b,
                   const float* __restrict__ w_tri) {
    int warp = threadIdx.x >> 5, lane = threadIdx.x & 31;
    int t = blockIdx.x * 8 + warp;

    float4 x = *(const float4*)&z[(size_t)t * CIN + lane * 4];
    float v1 = x.x + x.y + x.z + x.w;
    float v2 = x.x * x.x + x.y * x.y + x.z * x.z + x.w * x.w;
    #pragma unroll
    for (int off = 16; off; off >>= 1) {
        v1 += __shfl_xor_sync(~0u, v1, off);
        v2 += __shfl_xor_sync(~0u, v2, off);
    }
    float mean = v1 * (1.0f / CIN);
    float var  = v2 * (1.0f / CIN) - mean * mean;
    float rs   = rsqrtf(var + 1e-5f);

    float4 w = *(const float4*)&ln_w[lane * 4];
    float4 b = *(const float4*)&ln_b[lane * 4];
    float4 zn;
    zn.x = (x.x - mean) * rs * w.x + b.x;
    zn.y = (x.y - mean) * rs * w.y + b.y;
    zn.z = (x.z - mean) * rs * w.z + b.z;
    zn.w = (x.w - mean) * rs * w.w + b.w;
    uint2 u = { h2u(__floats2half2_rn(zn.x, zn.y)), h2u(__floats2half2_rn(zn.z, zn.w)) };
    *(uint2*)&g_znh[(size_t)t * CIN + lane * 4] = u;

    float p[4] = {};
    float zc[4] = { zn.x, zn.y, zn.z, zn.w };
    #pragma unroll
    for (int cc = 0; cc < 4; cc++) {
        float4 wt = *(const float4*)&w_tri[(lane * 4 + cc) * NH];
        p[0] += zc[cc] * wt.x; p[1] += zc[cc] * wt.y;
        p[2] += zc[cc] * wt.z; p[3] += zc[cc] * wt.w;
    }
    #pragma unroll
    for (int off = 16; off; off >>= 1)
        #pragma unroll
        for (int h = 0; h < 4; h++) p[h] += __shfl_xor_sync(~0u, p[h], off);
    if (lane == 0)
        #pragma unroll
        for (int h = 0; h < 4; h++)
            g_trih[(size_t)h * NTOK + t] = __float2half(p[h] * LOG2E);
}

// ============================================================
// Kernel 2: projections, fp16 mma. BM=128,BN=128,BK=128.
// ============================================================
constexpr int HS = 136;   // halves per smem row

__global__ __launch_bounds__(256, 2)
void proj_tc(const float* __restrict__ wq, const float* __restrict__ wk,
             const float* __restrict__ wv, const float* __restrict__ wg) {
    extern __shared__ __half smh[];
    __half* As = smh;                 // 128 x HS
    __half* Bs = smh + 128 * HS;      // 128 x HS
    int tid = threadIdx.x, lane = tid & 31, warp = tid >> 5;
    int g = lane >> 2, t = lane & 3;
    int sel = blockIdx.x;
    const float* W = (sel == 0) ? wq : (sel == 1) ? wk : (sel == 2) ? wv : wg;
    int m0 = blockIdx.y * 128;

    #pragma unroll
    for (int e = 0; e < 8; e++) {       // A: 2048 uint4
        int f = tid + e * 256;
        int row = f >> 4, c8 = (f & 15) * 8;
        *(uint4*)&As[row * HS + c8] = *(const uint4*)&g_znh[(size_t)(m0 + row) * CIN + c8];
    }
    #pragma unroll
    for (int e = 0; e < 16; e++) {      // B: 4096 float4 -> half
        int f = tid + e * 256;
        int row = f >> 5, c4 = (f & 31) * 4;
        float4 v = *(const float4*)&W[(size_t)row * CIN + c4];
        uint2 u = { h2u(__floats2half2_rn(v.x, v.y)), h2u(__floats2half2_rn(v.z, v.w)) };
        *(uint2*)&Bs[row * HS + c4] = u;
    }
    __syncthreads();

    int wm = warp >> 1, wn = warp & 1;   // 4x2, warp tile 32m x 64n
    float acc[2][8][4] = {};
    #pragma unroll
    for (int kc2 = 0; kc2 < 4; kc2++) {  // 32 c per iter
        uint32_t bf[8][4];
        #pragma unroll
        for (int nt = 0; nt < 8; nt++)
            ldm_x4t(bf[nt], &Bs[(kc2 * 32 + lane) * HS + wn * 64 + nt * 8]);
        #pragma unroll
        for (int kk = 0; kk < 2; kk++) {
            uint32_t af[2][4];
            #pragma unroll
            for (int mt = 0; mt < 2; mt++)
                ldm_x4(af[mt], &As[(wm * 32 + mt * 16 + (lane & 15)) * HS
                                   + (kc2 * 2 + kk) * 16 + (lane >> 4) * 8]);
            #pragma unroll
            for (int nt = 0; nt < 8; nt++) {
                mma16(acc[0][nt], af[0], &bf[nt][kk * 2]);
                mma16(acc[1][nt], af[1], &bf[nt][kk * 2]);
            }
        }
    }
    const float QS2 = QSCALE * LOG2E;
    #pragma unroll
    for (int mt = 0; mt < 2; mt++)
        #pragma unroll
        for (int nt = 0; nt < 8; nt++)
            #pragma unroll
            for (int hf = 0; hf < 2; hf++) {
                int gm  = m0 + wm * 32 + mt * 16 + g + hf * 8;
                int col = wn * 64 + nt * 8 + 2 * t;
                float c0 = acc[mt][nt][hf * 2 + 0], c1 = acc[mt][nt][hf * 2 + 1];
                size_t idx = (size_t)gm * CIN + col;
                if (sel == 0)
                    *(uint32_t*)&g_qh[idx] = h2u(__floats2half2_rn(c0 * QS2, c1 * QS2));
                else if (sel == 1)
                    *(uint32_t*)&g_kh[idx] = h2u(__floats2half2_rn(c0, c1));
                else if (sel == 2)
                    *(uint32_t*)&g_vh[idx] = h2u(__floats2half2_rn(c0, c1));
                else
                    *(uint32_t*)&g_gh[idx] = h2u(__floats2half2_rn(
                        1.0f / (1.0f + __expf(-c0)), 1.0f / (1.0f + __expf(-c1))));
            }
}

// ============================================================
// Kernel 3: attention, fp16 mma, warp-autonomous flash tiles,
// log2-domain softmax (ex2.approx), half tri bias.
// ============================================================
constexpr int KSS = 40;   // halves per K/V row

__global__ __launch_bounds__(256, 2)
void attn_tc(const float* __restrict__ mask) {
    int i = blockIdx.x, h = blockIdx.y;
    extern __shared__ __half smh[];
    __half* Ks  = smh;                  // 384 x 40
    __half* Vs  = smh + NSEQ * KSS;     // 384 x 40
    float*  bsm = (float*)(smh + 2 * NSEQ * KSS);  // 384

    int tid = threadIdx.x, lane = tid & 31, warp = tid >> 5;
    int g = lane >> 2, t = lane & 3;

    const __half* gK = g_kh + (size_t)(i * NSEQ) * CIN + h * CHD;
    const __half* gV = g_vh + (size_t)(i * NSEQ) * CIN + h * CHD;
    #pragma unroll
    for (int e = 0; e < 12; e++) {
        int f = tid + e * 256;              // 3072 4-half units
        int row = f >> 3, c4 = (f & 7) * 4;
        *(uint2*)&Ks[row * KSS + c4] = *(const uint2*)&gK[(size_t)row * CIN + c4];
        *(uint2*)&Vs[row * KSS + c4] = *(const uint2*)&gV[(size_t)row * CIN + c4];
    }
    {
        int k = tid;
        if (k < NSEQ) bsm[k] = LOG2E * 1e9f * (mask[i * NSEQ + k] - 1.0f);
        k += 256;
        if (k < NSEQ) bsm[k] = LOG2E * 1e9f * (mask[i * NSEQ + k] - 1.0f);
    }
    __syncthreads();

    const __half* trih = g_trih + (size_t)h * NTOK;

    for (int tile = warp; tile < 24; tile += 8) {
        int q0 = tile * 16;

        // Q fragments from global (half, pre-scaled)
        const __half* gQ = g_qh + (size_t)(i * NSEQ + q0) * CIN + h * CHD;
        uint32_t qa_[2][4];
        #pragma unroll
        for (int kc = 0; kc < 2; kc++) {
            qa_[kc][0] = *(const uint32_t*)&gQ[(size_t)g * CIN + kc * 16 + 2 * t];
            qa_[kc][1] = *(const uint32_t*)&gQ[(size_t)(g + 8) * CIN + kc * 16 + 2 * t];
            qa_[kc][2] = *(const uint32_t*)&gQ[(size_t)g * CIN + kc * 16 + 2 * t + 8];
            qa_[kc][3] = *(const uint32_t*)&gQ[(size_t)(g + 8) * CIN + kc * 16 + 2 * t + 8];
        }

        float M0 = -1e30f, M1 = -1e30f, l0 = 0.f, l1 = 0.f;
        float O[4][4] = {};

        #pragma unroll
        for (int ch = 0; ch < 4; ch++) {
            int k0c = ch * 96;

            // ---- QK scores (log2 domain) ----
            float s[12][4];
            #pragma unroll
            for (int nt = 0; nt < 12; nt++) {
                s[nt][0] = s[nt][1] = s[nt][2] = s[nt][3] = 0.f;
                uint32_t bf[4];
                ldm_x4(bf, &Ks[(k0c + nt * 8 + (lane & 7)) * KSS + (lane >> 3) * 8]);
                mma16(s[nt], qa_[0], &bf[0]);
                mma16(s[nt], qa_[1], &bf[2]);
            }

            // ---- biases (half tri) + chunk max ----
            int qa = q0 + g, qb = qa + 8;
            float cm0 = -1e30f, cm1 = -1e30f;
            #pragma unroll
            for (int nt = 0; nt < 12; nt++) {
                int k = k0c + nt * 8 + 2 * t;
                float2 bb = *(const float2*)&bsm[k];
                float2 t0 = __half22float2(*(const __half2*)&trih[(size_t)qa * NSEQ + k]);
                float2 t1 = __half22float2(*(const __half2*)&trih[(size_t)qb * NSEQ + k]);
                s[nt][0] += bb.x + t0.x; s[nt][1] += bb.y + t0.y;
                s[nt][2] += bb.x + t1.x; s[nt][3] += bb.y + t1.y;
                cm0 = fmaxf(cm0, fmaxf(s[nt][0], s[nt][1]));
                cm1 = fmaxf(cm1, fmaxf(s[nt][2], s[nt][3]));
            }
            cm0 = fmaxf(cm0, __shfl_xor_sync(~0u, cm0, 1));
            cm0 = fmaxf(cm0, __shfl_xor_sync(~0u, cm0, 2));
            cm1 = fmaxf(cm1, __shfl_xor_sync(~0u, cm1, 1));
            cm1 = fmaxf(cm1, __shfl_xor_sync(~0u, cm1, 2));

            // ---- online rescale (exp2 domain) ----
            float Mn0 = fmaxf(M0, cm0), Mn1 = fmaxf(M1, cm1);
            float al0 = fexp2(M0 - Mn0), al1 = fexp2(M1 - Mn1);
            M0 = Mn0; M1 = Mn1;
            l0 *= al0; l1 *= al1;
            #pragma unroll
            for (int ct = 0; ct < 4; ct++) {
                O[ct][0] *= al0; O[ct][1] *= al0;
                O[ct][2] *= al1; O[ct][3] *= al1;
            }

            // ---- exp2 + chunk sums ----
            float cs0 = 0.f, cs1 = 0.f;
            #pragma unroll
            for (int nt = 0; nt < 12; nt++) {
                s[nt][0] = fexp2(s[nt][0] - M0); cs0 += s[nt][0];
                s[nt][1] = fexp2(s[nt][1] - M0); cs0 += s[nt][1];
                s[nt][2] = fexp2(s[nt][2] - M1); cs1 += s[nt][2];
                s[nt][3] = fexp2(s[nt][3] - M1); cs1 += s[nt][3];
            }
            cs0 += __shfl_xor_sync(~0u, cs0, 1); cs0 += __shfl_xor_sync(~0u, cs0, 2);
            cs1 += __shfl_xor_sync(~0u, cs1, 1); cs1 += __shfl_xor_sync(~0u, cs1, 2);
            l0 += cs0; l1 += cs1;

            // ---- AV: P A-frags = register packs; V via ldmatrix.x4.trans ----
            #pragma unroll
            for (int j = 0; j < 6; j++) {       // k16 steps
                uint32_t pa[4];
                pa[0] = h2u(__floats2half2_rn(s[2 * j][0],     s[2 * j][1]));
                pa[1] = h2u(__floats2half2_rn(s[2 * j][2],     s[2 * j][3]));
                pa[2] = h2u(__floats2half2_rn(s[2 * j + 1][0], s[2 * j + 1][1]));
                pa[3] = h2u(__floats2half2_rn(s[2 * j + 1][2], s[2 * j + 1][3]));
                #pragma unroll
                for (int ct2 = 0; ct2 < 2; ct2++) {
                    uint32_t vb[4];
                    ldm_x4t(vb, &Vs[(k0c + j * 16 + (lane & 15)) * KSS
                                    + ct2 * 16 + (lane >> 4) * 8]);
                    mma16(O[ct2 * 2 + 0], pa, &vb[0]);
                    mma16(O[ct2 * 2 + 1], pa, &vb[2]);
                }
            }
        }

        // ---- normalize, gate (half), store og (half) ----
        float inv0 = 1.0f / l0, inv1 = 1.0f / l1;
        #pragma unroll
        for (int ct = 0; ct < 4; ct++) {
            int c = ct * 8 + 2 * t;
            size_t idx0 = (size_t)(i * NSEQ + q0 + g) * CIN + h * CHD + c;
            size_t idx1 = idx0 + (size_t)8 * CIN;
            float2 gg0 = __half22float2(*(const __half2*)&g_gh[idx0]);
            float2 gg1 = __half22float2(*(const __half2*)&g_gh[idx1]);
            *(uint32_t*)&g_ogh[idx0] = h2u(__floats2half2_rn(
                O[ct][0] * inv0 * gg0.x, O[ct][1] * inv0 * gg0.y));
            *(uint32_t*)&g_ogh[idx1] = h2u(__floats2half2_rn(
                O[ct][2] * inv1 * gg1.x, O[ct][3] * inv1 * gg1.y));
        }
    }
}

// ============================================================
// Kernel 4: out = og @ wo, fp16 mma. og already half.
// ============================================================
__global__ __launch_bounds__(256, 2)
void out_tc(const float* __restrict__ wo, float* __restrict__ out) {
    extern __shared__ __half smh[];
    __half* As = smh;
    __half* Bs = smh + 128 * HS;
    int tid = threadIdx.x, lane = tid & 31, warp = tid >> 5;
    int g = lane >> 2, t = lane & 3;
    int m0 = blockIdx.x * 128;

    #pragma unroll
    for (int e = 0; e < 8; e++) {       // A: 2048 uint4 (copies)
        int f = tid + e * 256;
        int row = f >> 4, c8 = (f & 15) * 8;
        *(uint4*)&As[row * HS + c8] = *(const uint4*)&g_ogh[(size_t)(m0 + row) * CIN + c8];
    }
    #pragma unroll
    for (int e = 0; e < 16; e++) {      // B: wo fp32 -> half
        int f = tid + e * 256;
        int row = f >> 5, c4 = (f & 31) * 4;
        float4 vb = *(const float4*)&wo[(size_t)row * CIN + c4];
        uint2 ub = { h2u(__floats2half2_rn(vb.x, vb.y)), h2u(__floats2half2_rn(vb.z, vb.w)) };
        *(uint2*)&Bs[row * HS + c4] = ub;
    }
    __syncthreads();

    int wm = warp >> 1, wn = warp & 1;
    float acc[2][8][4] = {};
    #pragma unroll
    for (int kc2 = 0; kc2 < 4; kc2++) {
        uint32_t bf[8][4];
        #pragma unroll
        for (int nt = 0; nt < 8; nt++)
            ldm_x4t(bf[nt], &Bs[(kc2 * 32 + lane) * HS + wn * 64 + nt * 8]);
        #pragma unroll
        for (int kk = 0; kk < 2; kk++) {
            uint32_t af[2][4];
            #pragma unroll
            for (int mt = 0; mt < 2; mt++)
                ldm_x4(af[mt], &As[(wm * 32 + mt * 16 + (lane & 15)) * HS
                                   + (kc2 * 2 + kk) * 16 + (lane >> 4) * 8]);
            #pragma unroll
            for (int nt = 0; nt < 8; nt++) {
                mma16(acc[0][nt], af[0], &bf[nt][kk * 2]);
                mma16(acc[1][nt], af[1], &bf[nt][kk * 2]);
            }
        }
    }
    #pragma unroll
    for (int mt = 0; mt < 2; mt++)
        #pragma unroll
        for (int nt = 0; nt < 8; nt++)
            #pragma unroll
            for (int hf = 0; hf < 2; hf++) {
                int gm  = m0 + wm * 32 + mt * 16 + g + hf * 8;
                int col = wn * 64 + nt * 8 + 2 * t;
                float2 o = { acc[mt][nt][hf * 2 + 0], acc[mt][nt][hf * 2 + 1] };
                *(float2*)&out[(size_t)gm * CIN + col] = o;
            }
}

// ============================================================
extern "C" void kernel_launch(void* const* d_in, const int* in_sizes, int n_in,
                              void* d_out, int out_size) {
    const float* z     = (const float*)d_in[0];
    const float* mask  = (const float*)d_in[1];
    const float* ln_w  = (const float*)d_in[2];
    const float* ln_b  = (const float*)d_in[3];
    const float* w_tri = (const float*)d_in[4];
    const float* wq    = (const float*)d_in[5];
    const float* wk    = (const float*)d_in[6];
    const float* wv    = (const float*)d_in[7];
    const float* wg    = (const float*)d_in[8];
    const float* wo    = (const float*)d_in[9];
    float* out = (float*)d_out;

    ln_tri_kernel<<<NTOK / 8, 256>>>(z, ln_w, ln_b, w_tri);

    size_t gemm_smem = (size_t)(2 * 128 * HS) * sizeof(__half);  // 69632
    cudaFuncSetAttribute(proj_tc, cudaFuncAttributeMaxDynamicSharedMemorySize, (int)gemm_smem);
    cudaFuncSetAttribute(out_tc,  cudaFuncAttributeMaxDynamicSharedMemorySize, (int)gemm_smem);

    dim3 gp(4, NTOK / 128);
    proj_tc<<<gp, 256, gemm_smem>>>(wq, wk, wv, wg);

    size_t att_smem = (size_t)(2 * NSEQ * KSS) * sizeof(__half) + NSEQ * sizeof(float); // 62976
    cudaFuncSetAttribute(attn_tc, cudaFuncAttributeMaxDynamicSharedMemorySize, (int)att_smem);
    dim3 ga(NSEQ, NH);
    attn_tc<<<ga, 256, att_smem>>>(mask);

    out_tc<<<NTOK / 128, 256, gemm_smem>>>(wo, out);
}